// round 1
// baseline (speedup 1.0000x reference)
#include <cuda_runtime.h>
#include <cstdint>
#include <cstddef>

// ---------------- problem constants ----------------
namespace {
constexpr int kT = 8192;       // tokens = B*S
constexpr int kD = 2048;
constexpr int kF = 4096;
constexpr int kE = 8;
constexpr int TM = 128;                     // CTA tile M and N
constexpr int ROWT = kT / TM + kE;          // 72 max padded row tiles
constexpr int TPAD = ROWT * TM;             // 9216 padded rows
constexpr int BK = 32;                      // K chunk
constexpr int NTH = 256;
constexpr int SMEM_BYTES = 2 * 2 * TM * BK * 4;  // A+B double buffered = 64 KB
}

// ---------------- scratch (static device globals; no runtime alloc) ----------
__device__ int g_counts[kE];
__device__ int g_cursor[kE];
__device__ int g_assign[kT];
__device__ int g_rowtoken[TPAD];
__device__ int g_tile_expert[ROWT];
__device__ float g_h1[(size_t)TPAD * kF];   // intermediate activations (tf32-rounded fp32)

// ---------------- helpers ----------------
__device__ __forceinline__ uint32_t cvt_tf32(float f) {
    uint32_t r;
    asm("cvt.rna.tf32.f32 %0, %1;" : "=r"(r) : "f"(f));
    return r;
}

// XOR swizzle at float4 granularity: conflict-free fragment loads + cp.async stores
__device__ __forceinline__ int swz(int m, int k) {
    return m * BK + ((((k >> 2) ^ (m & 7)) << 2) | (k & 3));
}

__device__ __forceinline__ void mma_tf32(float* c, const uint32_t* a, uint32_t b0, uint32_t b1) {
    asm volatile(
        "mma.sync.aligned.m16n8k8.row.col.f32.tf32.tf32.f32 "
        "{%0,%1,%2,%3}, {%4,%5,%6,%7}, {%8,%9}, {%0,%1,%2,%3};\n"
        : "+f"(c[0]), "+f"(c[1]), "+f"(c[2]), "+f"(c[3])
        : "r"(a[0]), "r"(a[1]), "r"(a[2]), "r"(a[3]), "r"(b0), "r"(b1));
}

__device__ __forceinline__ void cp_async16(uint32_t dst, const void* src, int src_sz) {
    asm volatile("cp.async.ca.shared.global [%0], [%1], 16, %2;\n"
                 :: "r"(dst), "l"(src), "r"(src_sz));
}

// ---------------- routing / permutation ----------------
__global__ void k_init() {
    int i = blockIdx.x * blockDim.x + threadIdx.x;
    if (i < kE) g_counts[i] = 0;
    if (i < TPAD) g_rowtoken[i] = -1;
}

__global__ void k_route(const float* __restrict__ logits) {
    int t = blockIdx.x * blockDim.x + threadIdx.x;
    if (t >= kT) return;
    const float* l = logits + (size_t)t * kE;
    int best = 0;
    float bv = l[0];
#pragma unroll
    for (int e = 1; e < kE; e++) {
        float v = l[e];
        if (v > bv) { bv = v; best = e; }   // strict > : first-max, matches jnp.argmax
    }
    g_assign[t] = best;
    atomicAdd(&g_counts[best], 1);
}

__global__ void k_offsets() {
    if (threadIdx.x != 0 || blockIdx.x != 0) return;
    int off = 0;
    for (int e = 0; e < kE; e++) {
        g_cursor[e] = off;
        int nt = (g_counts[e] + TM - 1) / TM;
        for (int i = 0; i < nt; i++) g_tile_expert[off / TM + i] = e;
        off += nt * TM;
    }
    for (int rt = off / TM; rt < ROWT; rt++) g_tile_expert[rt] = -1;
}

__global__ void k_scatter() {
    int t = blockIdx.x * blockDim.x + threadIdx.x;
    if (t >= kT) return;
    int e = g_assign[t];
    int pos = atomicAdd(&g_cursor[e], 1);   // order within expert irrelevant
    g_rowtoken[pos] = t;
}

// ---------------- tf32 tensor-core GEMM ----------------
// FIRST:  h1 = silu(x @ w1[e]^T)  : A rows gathered via g_rowtoken from hidden[T,D]
// !FIRST: out = h1 @ w2[e]^T      : A rows direct from g_h1, scatter to d_out
template <bool FIRST>
__global__ __launch_bounds__(NTH, 2) void k_gemm(
    const float* __restrict__ Ain,
    const float* __restrict__ W,
    float* __restrict__ out)
{
    constexpr int N = FIRST ? kF : kD;
    constexpr int K = FIRST ? kD : kF;
    const int rt = blockIdx.y;
    const int e = g_tile_expert[rt];
    if (e < 0) return;
    const int rowbase = rt * TM;
    const int colbase = blockIdx.x * TM;

    extern __shared__ float smem[];
    float* sA = smem;
    float* sB = smem + 2 * TM * BK;
    uint32_t sA_u, sB_u;
    {
        uint32_t b;
        asm("{ .reg .u64 t; cvta.to.shared.u64 t, %1; cvt.u32.u64 %0, t; }"
            : "=r"(b) : "l"(smem));
        sA_u = b;
        sB_u = b + 2u * TM * BK * 4u;
    }

    const int tid = threadIdx.x;
    const int lr = tid >> 3;   // 0..31 row within pass
    const int lq = tid & 7;    // float4 index along K

    const float* aptr[4];
#pragma unroll
    for (int p = 0; p < 4; p++) {
        int r = lr + p * 32;
        if (FIRST) {
            int tok = g_rowtoken[rowbase + r];
            aptr[p] = (tok >= 0) ? (Ain + (size_t)tok * kD) : nullptr;
        } else {
            aptr[p] = g_h1 + (size_t)(rowbase + r) * kF;
        }
    }
    const float* wrow[4];
#pragma unroll
    for (int p = 0; p < 4; p++) {
        int r = lr + p * 32;
        wrow[p] = W + (size_t)e * N * K + (size_t)(colbase + r) * K;
    }

    auto load_chunk = [&](int c, int buf) {
        int koff = c * BK + lq * 4;
        uint32_t abuf = sA_u + (uint32_t)(buf * TM * BK * 4);
        uint32_t bbuf = sB_u + (uint32_t)(buf * TM * BK * 4);
#pragma unroll
        for (int p = 0; p < 4; p++) {
            int r = lr + p * 32;
            uint32_t d = abuf + (uint32_t)((r * BK + ((lq ^ (r & 7)) << 2)) * 4);
            const float* s = aptr[p] ? (aptr[p] + koff) : (const float*)W;
            cp_async16(d, s, aptr[p] ? 16 : 0);   // src_sz=0 -> zero-fill pad rows
        }
#pragma unroll
        for (int p = 0; p < 4; p++) {
            int r = lr + p * 32;
            uint32_t d = bbuf + (uint32_t)((r * BK + ((lq ^ (r & 7)) << 2)) * 4);
            cp_async16(d, wrow[p] + koff, 16);
        }
    };

    const int warp = tid >> 5;
    const int lane = tid & 31;
    const int wm = warp & 1;    // m offset *64
    const int wn = warp >> 1;   // n offset *32
    const int gid = lane >> 2;  // 0..7
    const int tig = lane & 3;   // 0..3

    float acc[4][4][4];
#pragma unroll
    for (int i = 0; i < 4; i++)
#pragma unroll
        for (int j = 0; j < 4; j++)
#pragma unroll
            for (int q = 0; q < 4; q++) acc[i][j][q] = 0.f;

    constexpr int NC = K / BK;
    load_chunk(0, 0);
    asm volatile("cp.async.commit_group;\n");

    for (int c = 0; c < NC; c++) {
        int cur = c & 1;
        if (c + 1 < NC) {
            load_chunk(c + 1, cur ^ 1);
            asm volatile("cp.async.commit_group;\n");
            asm volatile("cp.async.wait_group 1;\n");
        } else {
            asm volatile("cp.async.wait_group 0;\n");
        }
        __syncthreads();
        const float* cA = sA + cur * TM * BK;
        const float* cB = sB + cur * TM * BK;
#pragma unroll
        for (int s = 0; s < 4; s++) {
            uint32_t af[4][4];
#pragma unroll
            for (int mi = 0; mi < 4; mi++) {
                int r0 = wm * 64 + mi * 16 + gid;
                int c0 = s * 8 + tig;
                if (FIRST) {
                    af[mi][0] = cvt_tf32(cA[swz(r0,     c0)]);
                    af[mi][1] = cvt_tf32(cA[swz(r0 + 8, c0)]);
                    af[mi][2] = cvt_tf32(cA[swz(r0,     c0 + 4)]);
                    af[mi][3] = cvt_tf32(cA[swz(r0 + 8, c0 + 4)]);
                } else {  // h1 already tf32-rounded at GEMM1 epilogue
                    af[mi][0] = __float_as_uint(cA[swz(r0,     c0)]);
                    af[mi][1] = __float_as_uint(cA[swz(r0 + 8, c0)]);
                    af[mi][2] = __float_as_uint(cA[swz(r0,     c0 + 4)]);
                    af[mi][3] = __float_as_uint(cA[swz(r0 + 8, c0 + 4)]);
                }
            }
#pragma unroll
            for (int nj = 0; nj < 4; nj++) {
                int n0 = wn * 32 + nj * 8 + gid;
                int c0 = s * 8 + tig;
                uint32_t b0 = cvt_tf32(cB[swz(n0, c0)]);
                uint32_t b1 = cvt_tf32(cB[swz(n0, c0 + 4)]);
#pragma unroll
                for (int mi = 0; mi < 4; mi++) mma_tf32(acc[mi][nj], af[mi], b0, b1);
            }
        }
        __syncthreads();
    }

    // ---- epilogue ----
#pragma unroll
    for (int mi = 0; mi < 4; mi++) {
#pragma unroll
        for (int rr = 0; rr < 2; rr++) {
            int lrow = wm * 64 + mi * 16 + gid + rr * 8;
            if (FIRST) {
                float* hrow = g_h1 + (size_t)(rowbase + lrow) * kF + colbase;
#pragma unroll
                for (int nj = 0; nj < 4; nj++) {
                    int lcol = wn * 32 + nj * 8 + tig * 2;
                    float v0 = acc[mi][nj][rr * 2 + 0];
                    float v1 = acc[mi][nj][rr * 2 + 1];
                    v0 = v0 / (1.f + __expf(-v0));   // SiLU
                    v1 = v1 / (1.f + __expf(-v1));
                    float2 st;
                    st.x = __uint_as_float(cvt_tf32(v0));  // pre-round for GEMM2
                    st.y = __uint_as_float(cvt_tf32(v1));
                    *(float2*)(hrow + lcol) = st;
                }
            } else {
                int tok = g_rowtoken[rowbase + lrow];
                if (tok >= 0) {
                    float* orow = out + (size_t)tok * kD + colbase;
#pragma unroll
                    for (int nj = 0; nj < 4; nj++) {
                        int lcol = wn * 32 + nj * 8 + tig * 2;
                        float2 st;
                        st.x = acc[mi][nj][rr * 2 + 0];
                        st.y = acc[mi][nj][rr * 2 + 1];
                        *(float2*)(orow + lcol) = st;
                    }
                }
            }
        }
    }
}

// ---------------- entry ----------------
extern "C" void kernel_launch(void* const* d_in, const int* in_sizes, int n_in,
                              void* d_out, int out_size) {
    const float* hs     = (const float*)d_in[0];  // [B,S,D] fp32
    const float* logits = (const float*)d_in[1];  // [B,S,E] fp32
    const float* w1     = (const float*)d_in[2];  // [E,F,D] fp32
    const float* w2     = (const float*)d_in[3];  // [E,D,F] fp32
    float* out = (float*)d_out;

    cudaFuncSetAttribute(k_gemm<true>,  cudaFuncAttributeMaxDynamicSharedMemorySize, SMEM_BYTES);
    cudaFuncSetAttribute(k_gemm<false>, cudaFuncAttributeMaxDynamicSharedMemorySize, SMEM_BYTES);

    k_init<<<(TPAD + 255) / 256, 256>>>();
    k_route<<<kT / 256, 256>>>(logits);
    k_offsets<<<1, 32>>>();
    k_scatter<<<kT / 256, 256>>>();

    dim3 g1(kF / TM, ROWT);   // col-tile fastest -> wave-level L2 reuse of weights
    k_gemm<true><<<g1, NTH, SMEM_BYTES>>>(hs, w1, nullptr);
    dim3 g2(kD / TM, ROWT);
    k_gemm<false><<<g2, NTH, SMEM_BYTES>>>(nullptr, w2, out);
}

// round 2
// speedup vs baseline: 1.6313x; 1.6313x over previous
#include <cuda_runtime.h>
#include <cuda_fp16.h>
#include <cstdint>
#include <cstddef>

// ---------------- problem constants ----------------
namespace {
constexpr int kT = 8192;       // tokens = B*S
constexpr int kD = 2048;
constexpr int kF = 4096;
constexpr int kE = 8;
constexpr int TM = 128;                     // CTA tile M and N
constexpr int ROWT = kT / TM + kE;          // 72 max padded row tiles
constexpr int TPAD = ROWT * TM;             // 9216 padded rows
constexpr int BK = 64;                      // K chunk in halves (128 bytes/row)
constexpr int NTH = 256;
constexpr int TILE_BYTES = TM * BK * 2;     // 16 KB per tile
constexpr int SMEM_BYTES = 2 * 2 * TILE_BYTES;  // A+B double buffered = 64 KB
}

// ---------------- scratch (static device globals; no runtime alloc) ----------
__device__ int g_counts[kE];
__device__ int g_cursor[kE];
__device__ int g_assign[kT];
__device__ int g_rowtoken[TPAD];
__device__ int g_tile_expert[ROWT];
__device__ __half g_xh[(size_t)kT * kD];          // fp16 hidden states
__device__ __half g_w1h[(size_t)kE * kF * kD];    // fp16 w1
__device__ __half g_w2h[(size_t)kE * kD * kF];    // fp16 w2
__device__ __half g_h1h[(size_t)TPAD * kF];       // fp16 intermediate silu(x@w1^T)

// ---------------- helpers ----------------
// XOR swizzle at 16-byte (8-half) granularity within a 128-byte row
__device__ __forceinline__ int swzh(int r, int k) {
    return r * BK + (((((k) >> 3) ^ (r & 7)) << 3) | (k & 7));
}

__device__ __forceinline__ void mma_f16(float* c, const uint32_t* a, uint32_t b0, uint32_t b1) {
    asm volatile(
        "mma.sync.aligned.m16n8k16.row.col.f32.f16.f16.f32 "
        "{%0,%1,%2,%3}, {%4,%5,%6,%7}, {%8,%9}, {%0,%1,%2,%3};\n"
        : "+f"(c[0]), "+f"(c[1]), "+f"(c[2]), "+f"(c[3])
        : "r"(a[0]), "r"(a[1]), "r"(a[2]), "r"(a[3]), "r"(b0), "r"(b1));
}

__device__ __forceinline__ void cp_async16(uint32_t dst, const void* src, int src_sz) {
    asm volatile("cp.async.ca.shared.global [%0], [%1], 16, %2;\n"
                 :: "r"(dst), "l"(src), "r"(src_sz));
}

// ---------------- fp32 -> fp16 bulk convert (8 elems / thread) ----------------
__global__ void k_cvt(const float4* __restrict__ src, uint4* __restrict__ dst, int n8) {
    int i = blockIdx.x * blockDim.x + threadIdx.x;
    if (i >= n8) return;
    float4 a = src[2 * i];
    float4 b = src[2 * i + 1];
    __half2 h0 = __floats2half2_rn(a.x, a.y);
    __half2 h1 = __floats2half2_rn(a.z, a.w);
    __half2 h2 = __floats2half2_rn(b.x, b.y);
    __half2 h3 = __floats2half2_rn(b.z, b.w);
    uint4 o;
    o.x = *(uint32_t*)&h0; o.y = *(uint32_t*)&h1;
    o.z = *(uint32_t*)&h2; o.w = *(uint32_t*)&h3;
    dst[i] = o;
}

// ---------------- routing / permutation ----------------
__global__ void k_init() {
    int i = blockIdx.x * blockDim.x + threadIdx.x;
    if (i < kE) g_counts[i] = 0;
    if (i < TPAD) g_rowtoken[i] = -1;
}

__global__ void k_route(const float* __restrict__ logits) {
    int t = blockIdx.x * blockDim.x + threadIdx.x;
    if (t >= kT) return;
    const float* l = logits + (size_t)t * kE;
    int best = 0;
    float bv = l[0];
#pragma unroll
    for (int e = 1; e < kE; e++) {
        float v = l[e];
        if (v > bv) { bv = v; best = e; }   // strict > : first-max, matches jnp.argmax
    }
    g_assign[t] = best;
    atomicAdd(&g_counts[best], 1);
}

__global__ void k_offsets() {
    if (threadIdx.x != 0 || blockIdx.x != 0) return;
    int off = 0;
    for (int e = 0; e < kE; e++) {
        g_cursor[e] = off;
        int nt = (g_counts[e] + TM - 1) / TM;
        for (int i = 0; i < nt; i++) g_tile_expert[off / TM + i] = e;
        off += nt * TM;
    }
    for (int rt = off / TM; rt < ROWT; rt++) g_tile_expert[rt] = -1;
}

__global__ void k_scatter() {
    int t = blockIdx.x * blockDim.x + threadIdx.x;
    if (t >= kT) return;
    int e = g_assign[t];
    int pos = atomicAdd(&g_cursor[e], 1);   // order within expert irrelevant
    g_rowtoken[pos] = t;
}

// ---------------- fp16 tensor-core GEMM ----------------
// FIRST:  h1 = silu(x @ w1[e]^T)  : A rows gathered via g_rowtoken from g_xh
// !FIRST: out = h1 @ w2[e]^T      : A rows direct from g_h1h, scatter fp32 to d_out
template <bool FIRST>
__global__ __launch_bounds__(NTH, 2) void k_gemm(float* __restrict__ out)
{
    constexpr int N = FIRST ? kF : kD;
    constexpr int K = FIRST ? kD : kF;
    const int rt = blockIdx.y;
    const int e = g_tile_expert[rt];
    if (e < 0) return;
    const int rowbase = rt * TM;
    const int colbase = blockIdx.x * TM;

    extern __shared__ __half smem[];
    __half* sA = smem;                       // [2][TM][BK]
    __half* sB = smem + 2 * TM * BK;
    uint32_t sA_u, sB_u;
    {
        uint32_t b;
        asm("{ .reg .u64 t; cvta.to.shared.u64 t, %1; cvt.u32.u64 %0, t; }"
            : "=r"(b) : "l"(smem));
        sA_u = b;
        sB_u = b + 2u * TILE_BYTES;
    }

    const int tid = threadIdx.x;
    const int lr = tid >> 3;   // 0..31 row within pass
    const int lq = tid & 7;    // 16-byte group along K

    const __half* aptr[4];
#pragma unroll
    for (int p = 0; p < 4; p++) {
        int r = lr + p * 32;
        if (FIRST) {
            int tok = g_rowtoken[rowbase + r];
            aptr[p] = (tok >= 0) ? (g_xh + (size_t)tok * kD) : nullptr;
        } else {
            aptr[p] = g_h1h + (size_t)(rowbase + r) * kF;
        }
    }
    const __half* wbase = FIRST ? g_w1h : g_w2h;
    const __half* wrow[4];
#pragma unroll
    for (int p = 0; p < 4; p++) {
        int r = lr + p * 32;
        wrow[p] = wbase + (size_t)e * N * K + (size_t)(colbase + r) * K;
    }

    auto load_chunk = [&](int c, int buf) {
        int koff = c * BK + lq * 8;
        uint32_t abuf = sA_u + (uint32_t)(buf * TILE_BYTES);
        uint32_t bbuf = sB_u + (uint32_t)(buf * TILE_BYTES);
#pragma unroll
        for (int p = 0; p < 4; p++) {
            int r = lr + p * 32;
            uint32_t d = abuf + (uint32_t)((r * BK + ((lq ^ (r & 7)) << 3)) * 2);
            const __half* s = aptr[p] ? (aptr[p] + koff) : g_w1h;
            cp_async16(d, s, aptr[p] ? 16 : 0);   // src_sz=0 -> zero-fill pad rows
        }
#pragma unroll
        for (int p = 0; p < 4; p++) {
            int r = lr + p * 32;
            uint32_t d = bbuf + (uint32_t)((r * BK + ((lq ^ (r & 7)) << 3)) * 2);
            cp_async16(d, wrow[p] + koff, 16);
        }
    };

    const int warp = tid >> 5;
    const int lane = tid & 31;
    const int wm = warp & 1;    // m offset *64
    const int wn = warp >> 1;   // n offset *32
    const int gid = lane >> 2;  // 0..7
    const int tig = lane & 3;   // 0..3

    float acc[4][4][4];
#pragma unroll
    for (int i = 0; i < 4; i++)
#pragma unroll
        for (int j = 0; j < 4; j++)
#pragma unroll
            for (int q = 0; q < 4; q++) acc[i][j][q] = 0.f;

    constexpr int NC = K / BK;
    load_chunk(0, 0);
    asm volatile("cp.async.commit_group;\n");

    for (int c = 0; c < NC; c++) {
        int cur = c & 1;
        if (c + 1 < NC) {
            load_chunk(c + 1, cur ^ 1);
            asm volatile("cp.async.commit_group;\n");
            asm volatile("cp.async.wait_group 1;\n");
        } else {
            asm volatile("cp.async.wait_group 0;\n");
        }
        __syncthreads();
        const __half* cA = sA + cur * TM * BK;
        const __half* cB = sB + cur * TM * BK;
#pragma unroll
        for (int s = 0; s < 4; s++) {       // 4 k-steps of 16
            const int k0 = s * 16;
            const int kb = k0 + tig * 2;
            uint32_t af[4][4];
#pragma unroll
            for (int mi = 0; mi < 4; mi++) {
                int r0 = wm * 64 + mi * 16 + gid;
                af[mi][0] = *(const uint32_t*)(cA + swzh(r0,     kb));
                af[mi][1] = *(const uint32_t*)(cA + swzh(r0 + 8, kb));
                af[mi][2] = *(const uint32_t*)(cA + swzh(r0,     kb + 8));
                af[mi][3] = *(const uint32_t*)(cA + swzh(r0 + 8, kb + 8));
            }
#pragma unroll
            for (int nj = 0; nj < 4; nj++) {
                int n0 = wn * 32 + nj * 8 + gid;
                uint32_t b0 = *(const uint32_t*)(cB + swzh(n0, kb));
                uint32_t b1 = *(const uint32_t*)(cB + swzh(n0, kb + 8));
#pragma unroll
                for (int mi = 0; mi < 4; mi++) mma_f16(acc[mi][nj], af[mi], b0, b1);
            }
        }
        __syncthreads();
    }

    // ---- epilogue ----
#pragma unroll
    for (int mi = 0; mi < 4; mi++) {
#pragma unroll
        for (int rr = 0; rr < 2; rr++) {
            int lrow = wm * 64 + mi * 16 + gid + rr * 8;
            if (FIRST) {
                __half* hrow = g_h1h + (size_t)(rowbase + lrow) * kF + colbase;
#pragma unroll
                for (int nj = 0; nj < 4; nj++) {
                    int lcol = wn * 32 + nj * 8 + tig * 2;
                    float v0 = acc[mi][nj][rr * 2 + 0];
                    float v1 = acc[mi][nj][rr * 2 + 1];
                    v0 = v0 / (1.f + __expf(-v0));   // SiLU
                    v1 = v1 / (1.f + __expf(-v1));
                    __half2 h = __floats2half2_rn(v0, v1);
                    *(uint32_t*)(hrow + lcol) = *(uint32_t*)&h;
                }
            } else {
                int tok = g_rowtoken[rowbase + lrow];
                if (tok >= 0) {
                    float* orow = out + (size_t)tok * kD + colbase;
#pragma unroll
                    for (int nj = 0; nj < 4; nj++) {
                        int lcol = wn * 32 + nj * 8 + tig * 2;
                        float2 st;
                        st.x = acc[mi][nj][rr * 2 + 0];
                        st.y = acc[mi][nj][rr * 2 + 1];
                        *(float2*)(orow + lcol) = st;
                    }
                }
            }
        }
    }
}

// ---------------- entry ----------------
extern "C" void kernel_launch(void* const* d_in, const int* in_sizes, int n_in,
                              void* d_out, int out_size) {
    const float* hs     = (const float*)d_in[0];  // [B,S,D] fp32
    const float* logits = (const float*)d_in[1];  // [B,S,E] fp32
    const float* w1     = (const float*)d_in[2];  // [E,F,D] fp32
    const float* w2     = (const float*)d_in[3];  // [E,D,F] fp32
    float* out = (float*)d_out;

    cudaFuncSetAttribute(k_gemm<true>,  cudaFuncAttributeMaxDynamicSharedMemorySize, SMEM_BYTES);
    cudaFuncSetAttribute(k_gemm<false>, cudaFuncAttributeMaxDynamicSharedMemorySize, SMEM_BYTES);

    // resolve scratch symbol addresses (query only — no allocation)
    void *p_xh, *p_w1h, *p_w2h;
    cudaGetSymbolAddress(&p_xh,  g_xh);
    cudaGetSymbolAddress(&p_w1h, g_w1h);
    cudaGetSymbolAddress(&p_w2h, g_w2h);

    // fp32 -> fp16 conversions
    {
        int n8 = (kT * kD) / 8;
        k_cvt<<<(n8 + 255) / 256, 256>>>((const float4*)hs, (uint4*)p_xh, n8);
    }
    {
        int n8 = (kE * (size_t)kF * kD) / 8;
        k_cvt<<<(n8 + 255) / 256, 256>>>((const float4*)w1, (uint4*)p_w1h, n8);
    }
    {
        int n8 = (kE * (size_t)kD * kF) / 8;
        k_cvt<<<(n8 + 255) / 256, 256>>>((const float4*)w2, (uint4*)p_w2h, n8);
    }

    // routing
    k_init<<<(TPAD + 255) / 256, 256>>>();
    k_route<<<kT / 256, 256>>>(logits);
    k_offsets<<<1, 32>>>();
    k_scatter<<<kT / 256, 256>>>();

    // expert GEMMs (col-tile fastest -> wave-level L2 reuse of weights)
    dim3 g1(kF / TM, ROWT);
    k_gemm<true><<<g1, NTH, SMEM_BYTES>>>(nullptr);
    dim3 g2(kD / TM, ROWT);
    k_gemm<false><<<g2, NTH, SMEM_BYTES>>>(out);
}

// round 4
// speedup vs baseline: 2.8769x; 1.7635x over previous
#include <cuda_runtime.h>
#include <cuda_fp16.h>
#include <cstdint>
#include <cstddef>

// ---------------- problem constants ----------------
namespace {
constexpr int kT = 8192, kD = 2048, kF = 4096, kE = 8;
constexpr int TMm = 128;                 // CTA tile M
constexpr int TN  = 256;                 // CTA tile N
constexpr int ROWT = kT / TMm + kE;      // 72 padded row tiles max
constexpr int TPAD = ROWT * TMm;         // 9216
constexpr int BK = 64;                   // halves per K chunk (128 B rows)
constexpr int ST = 3;                    // pipeline stages
constexpr int A_BYTES = TMm * BK * 2;    // 16 KB
constexpr int B_BYTES = TN * BK * 2;     // 32 KB
constexpr int STG = A_BYTES + B_BYTES;   // 48 KB
constexpr int SMEM_BYTES = ST * STG;     // 144 KB
constexpr int NTH = 256;                 // 8 warps
}

// ---------------- scratch globals ----------------
__device__ int g_counts[kE];
__device__ int g_cursor[kE];
__device__ int g_rowtoken[TPAD];
__device__ int g_tile_expert[ROWT];
__device__ __half g_xperm[(size_t)TPAD * kD];     // permuted+padded fp16 tokens
__device__ __half g_w1h[(size_t)kE * kF * kD];
__device__ __half g_w2h[(size_t)kE * kD * kF];
__device__ __half g_h1h[(size_t)TPAD * kF];       // silu(x@w1^T) fp16

// ---------------- helpers ----------------
__device__ __forceinline__ uint32_t smem_u32(const void* p) {
    uint32_t a;
    asm("{ .reg .u64 t; cvta.to.shared.u64 t, %1; cvt.u32.u64 %0, t; }" : "=r"(a) : "l"(p));
    return a;
}
__device__ __forceinline__ void ldsm_x4(uint32_t* r, uint32_t addr) {
    asm volatile("ldmatrix.sync.aligned.m8n8.x4.shared.b16 {%0,%1,%2,%3}, [%4];"
                 : "=r"(r[0]), "=r"(r[1]), "=r"(r[2]), "=r"(r[3]) : "r"(addr));
}
__device__ __forceinline__ void mma_f16(float* c, const uint32_t* a, uint32_t b0, uint32_t b1) {
    asm volatile(
        "mma.sync.aligned.m16n8k16.row.col.f32.f16.f16.f32 "
        "{%0,%1,%2,%3}, {%4,%5,%6,%7}, {%8,%9}, {%0,%1,%2,%3};\n"
        : "+f"(c[0]), "+f"(c[1]), "+f"(c[2]), "+f"(c[3])
        : "r"(a[0]), "r"(a[1]), "r"(a[2]), "r"(a[3]), "r"(b0), "r"(b1));
}
__device__ __forceinline__ void cp_async16(uint32_t dst, const void* src) {
    asm volatile("cp.async.cg.shared.global [%0], [%1], 16;" :: "r"(dst), "l"(src));
}

// ---------------- fp32 -> fp16 bulk convert ----------------
__global__ void k_cvt(const float4* __restrict__ src, uint4* __restrict__ dst, int n8) {
    int i = blockIdx.x * blockDim.x + threadIdx.x;
    if (i >= n8) return;
    float4 a = src[2 * i], b = src[2 * i + 1];
    __half2 h0 = __floats2half2_rn(a.x, a.y), h1 = __floats2half2_rn(a.z, a.w);
    __half2 h2 = __floats2half2_rn(b.x, b.y), h3 = __floats2half2_rn(b.z, b.w);
    uint4 o;
    o.x = *(uint32_t*)&h0; o.y = *(uint32_t*)&h1;
    o.z = *(uint32_t*)&h2; o.w = *(uint32_t*)&h3;
    dst[i] = o;
}

// ---------------- routing ----------------
__global__ void k_init() {
    int i = blockIdx.x * blockDim.x + threadIdx.x;
    if (i < kE) g_counts[i] = 0;
    if (i < TPAD) g_rowtoken[i] = -1;
}
__global__ void k_route(const float* __restrict__ logits) {
    int t = blockIdx.x * blockDim.x + threadIdx.x;
    if (t >= kT) return;
    const float* l = logits + (size_t)t * kE;
    int best = 0; float bv = l[0];
#pragma unroll
    for (int e = 1; e < kE; e++) { float v = l[e]; if (v > bv) { bv = v; best = e; } }
    atomicAdd(&g_counts[best], 1);
    ((int*)g_xperm)[t] = best;     // temp storage, overwritten by k_permute later
}
__global__ void k_offsets() {
    if (threadIdx.x != 0 || blockIdx.x != 0) return;
    int off = 0;
    for (int e = 0; e < kE; e++) {
        g_cursor[e] = off;
        int nt = (g_counts[e] + TMm - 1) / TMm;
        for (int i = 0; i < nt; i++) g_tile_expert[off / TMm + i] = e;
        off += nt * TMm;
    }
    for (int rt = off / TMm; rt < ROWT; rt++) g_tile_expert[rt] = -1;
}
__global__ void k_scatter() {
    int t = blockIdx.x * blockDim.x + threadIdx.x;
    if (t >= kT) return;
    int e = ((int*)g_xperm)[t];
    int pos = atomicAdd(&g_cursor[e], 1);
    g_rowtoken[pos] = t;
}
// gather + fp32->fp16 convert + zero-pad into [TPAD, kD]
__global__ void k_permute(const float4* __restrict__ hs) {
    int i = blockIdx.x * blockDim.x + threadIdx.x;   // one per 8 halves
    int row = i >> 8;                                // kD/8 = 256 groups/row
    int q = i & 255;
    if (row >= TPAD) return;
    int tok = g_rowtoken[row];
    uint4 o = make_uint4(0, 0, 0, 0);
    if (tok >= 0) {
        const float4* s = hs + (size_t)tok * (kD / 4) + 2 * q;
        float4 a = s[0], b = s[1];
        __half2 h0 = __floats2half2_rn(a.x, a.y), h1 = __floats2half2_rn(a.z, a.w);
        __half2 h2 = __floats2half2_rn(b.x, b.y), h3 = __floats2half2_rn(b.z, b.w);
        o.x = *(uint32_t*)&h0; o.y = *(uint32_t*)&h1;
        o.z = *(uint32_t*)&h2; o.w = *(uint32_t*)&h3;
    }
    ((uint4*)g_xperm)[(size_t)row * 256 + q] = o;
}

// ---------------- fp16 HMMA GEMM (ldmatrix + 3-stage cp.async) ----------------
// CTA tile 128x256, 8 warps (2 M x 4 N), warp tile 64x64.
// FIRST:  h1[TPAD,kF] = silu(g_xperm @ w1[e]^T)
// !FIRST: out[tok,kD] = g_h1h @ w2[e]^T   (scatter; pad rows dropped)
template <bool FIRST>
__global__ __launch_bounds__(NTH, 1) void k_gemm(float* __restrict__ out)
{
    constexpr int N = FIRST ? kF : kD;
    constexpr int K = FIRST ? kD : kF;
    constexpr int NC = K / BK;
    const int rt = blockIdx.y;
    const int e = g_tile_expert[rt];
    if (e < 0) return;
    const int rowbase = rt * TMm;
    const int colbase = blockIdx.x * TN;

    extern __shared__ char smem[];
    const uint32_t sb = smem_u32(smem);
    const int tid = threadIdx.x;
    const int warp = tid >> 5, lane = tid & 31;
    const int wm = warp & 1, wn = warp >> 1;

    const __half* Abase = FIRST ? g_xperm : g_h1h;
    const __half* Wb = (FIRST ? g_w1h : g_w2h) + (size_t)e * ((size_t)N * K);

    // ---- cp.async mapping: q = 16B group along K, r = base row ----
    const int q = tid & 7, r = tid >> 3;                 // r: 0..31
    const __half* aptr = Abase + (size_t)(rowbase + r) * K + q * 8;
    const __half* bptr = Wb + (size_t)(colbase + r) * K + q * 8;
    const uint32_t dA = (uint32_t)(r * 128 + ((q ^ (r & 7)) << 4));  // p*32 preserves row&7

    auto prefetch = [&](int c) {
        const uint32_t base = sb + (uint32_t)((c % ST) * STG);
        const __half* ap = aptr + c * BK;
#pragma unroll
        for (int p = 0; p < 4; p++)
            cp_async16(base + dA + (uint32_t)(p * 32 * 128), ap + (size_t)p * 32 * K);
        const __half* bp = bptr + c * BK;
#pragma unroll
        for (int p = 0; p < 8; p++)
            cp_async16(base + A_BYTES + dA + (uint32_t)(p * 32 * 128), bp + (size_t)p * 32 * K);
        asm volatile("cp.async.commit_group;" ::: "memory");
    };

    prefetch(0);
    prefetch(1);

    // ---- ldmatrix lane geometry ----
    // A x4 (16 rows x 16 k): lane -> row rowA+mi*16, k-group kgA
    const int rowA = wm * 64 + (lane & 15);
    const int kgA = lane >> 4;
    // B x4 (two nj tiles: 16 n-rows x 16 k): lane -> row rowB+nj2*16, k-group kgB
    const int rowB = wn * 64 + ((lane >> 4) << 3) + (lane & 7);
    const int kgB = (lane >> 3) & 1;

    float acc[4][8][4];
#pragma unroll
    for (int i = 0; i < 4; i++)
#pragma unroll
        for (int j = 0; j < 8; j++)
#pragma unroll
            for (int v = 0; v < 4; v++) acc[i][j][v] = 0.f;

    for (int c = 0; c < NC; c++) {
        if (c + 1 < NC) asm volatile("cp.async.wait_group 1;" ::: "memory");
        else            asm volatile("cp.async.wait_group 0;" ::: "memory");
        __syncthreads();
        if (c + 2 < NC) prefetch(c + 2);

        const uint32_t stA = sb + (uint32_t)((c % ST) * STG);
        const uint32_t stB = stA + A_BYTES;
#pragma unroll
        for (int s = 0; s < 4; s++) {     // 4 k16-steps
            uint32_t a[4][4];
#pragma unroll
            for (int mi = 0; mi < 4; mi++) {
                const int rr = rowA + mi * 16;
                ldsm_x4(a[mi], stA + (uint32_t)(rr * 128 + (((2 * s + kgA) ^ (rr & 7)) << 4)));
            }
            uint32_t b[4][4];
#pragma unroll
            for (int nj2 = 0; nj2 < 4; nj2++) {
                const int rr = rowB + nj2 * 16;
                ldsm_x4(b[nj2], stB + (uint32_t)(rr * 128 + (((2 * s + kgB) ^ (rr & 7)) << 4)));
            }
#pragma unroll
            for (int mi = 0; mi < 4; mi++)
#pragma unroll
                for (int nj = 0; nj < 8; nj++)
                    mma_f16(acc[mi][nj], a[mi], b[nj >> 1][(nj & 1) * 2], b[nj >> 1][(nj & 1) * 2 + 1]);
        }
        __syncthreads();
    }

    // ---- epilogue ----
    const int g = lane >> 2, tig = lane & 3;
#pragma unroll
    for (int mi = 0; mi < 4; mi++) {
#pragma unroll
        for (int rr = 0; rr < 2; rr++) {
            const int lrow = rowbase + wm * 64 + mi * 16 + g + rr * 8;
            if (FIRST) {
                __half* hp = g_h1h + (size_t)lrow * kF + colbase;
#pragma unroll
                for (int nj = 0; nj < 8; nj++) {
                    const int col = wn * 64 + nj * 8 + tig * 2;
                    float v0 = acc[mi][nj][rr * 2 + 0];
                    float v1 = acc[mi][nj][rr * 2 + 1];
                    v0 = v0 / (1.f + __expf(-v0));       // SiLU
                    v1 = v1 / (1.f + __expf(-v1));
                    __half2 h = __floats2half2_rn(v0, v1);
                    *(uint32_t*)(hp + col) = *(uint32_t*)&h;
                }
            } else {
                const int tok = g_rowtoken[lrow];
                if (tok >= 0) {
                    float* op = out + (size_t)tok * kD + colbase;
#pragma unroll
                    for (int nj = 0; nj < 8; nj++) {
                        const int col = wn * 64 + nj * 8 + tig * 2;
                        float2 st;
                        st.x = acc[mi][nj][rr * 2 + 0];
                        st.y = acc[mi][nj][rr * 2 + 1];
                        *(float2*)(op + col) = st;
                    }
                }
            }
        }
    }
}

// ---------------- entry ----------------
extern "C" void kernel_launch(void* const* d_in, const int* in_sizes, int n_in,
                              void* d_out, int out_size) {
    const float* hs     = (const float*)d_in[0];
    const float* logits = (const float*)d_in[1];
    const float* w1     = (const float*)d_in[2];
    const float* w2     = (const float*)d_in[3];
    float* out = (float*)d_out;

    cudaFuncSetAttribute(k_gemm<true>,  cudaFuncAttributeMaxDynamicSharedMemorySize, SMEM_BYTES);
    cudaFuncSetAttribute(k_gemm<false>, cudaFuncAttributeMaxDynamicSharedMemorySize, SMEM_BYTES);

    void *p_w1h, *p_w2h;
    cudaGetSymbolAddress(&p_w1h, g_w1h);
    cudaGetSymbolAddress(&p_w2h, g_w2h);

    // weight fp32 -> fp16
    {
        long long n8 = ((long long)kE * kF * kD) / 8;
        k_cvt<<<(unsigned)((n8 + 255) / 256), 256>>>((const float4*)w1, (uint4*)p_w1h, (int)n8);
    }
    {
        long long n8 = ((long long)kE * kD * kF) / 8;
        k_cvt<<<(unsigned)((n8 + 255) / 256), 256>>>((const float4*)w2, (uint4*)p_w2h, (int)n8);
    }

    // routing + permuted fp16 activations
    k_init<<<(TPAD + 255) / 256, 256>>>();
    k_route<<<kT / 256, 256>>>(logits);
    k_offsets<<<1, 32>>>();
    k_scatter<<<kT / 256, 256>>>();
    k_permute<<<TPAD, 256>>>((const float4*)hs);

    dim3 g1(kF / TN, ROWT);
    k_gemm<true><<<g1, NTH, SMEM_BYTES>>>(nullptr);
    dim3 g2(kD / TN, ROWT);
    k_gemm<false><<<g2, NTH, SMEM_BYTES>>>(out);
}

// round 5
// speedup vs baseline: 3.0464x; 1.0589x over previous
#include <cuda_runtime.h>
#include <cuda_fp16.h>
#include <cstdint>
#include <cstddef>

// ---------------- problem constants ----------------
namespace {
constexpr int kT = 8192, kD = 2048, kF = 4096, kE = 8;
constexpr int TMm = 128;                 // CTA tile M
constexpr int TN  = 256;                 // CTA tile N
constexpr int ROWT = kT / TMm + kE;      // 72 padded row tiles max
constexpr int TPAD = ROWT * TMm;         // 9216
constexpr int BK = 64;                   // halves per K chunk (128 B rows)
constexpr int ST = 4;                    // pipeline stages
constexpr int A_BYTES = TMm * BK * 2;    // 16 KB
constexpr int B_BYTES = TN * BK * 2;     // 32 KB
constexpr int STG = A_BYTES + B_BYTES;   // 48 KB
constexpr int SMEM_BYTES = ST * STG;     // 192 KB
constexpr int NTH = 256;                 // 8 warps
// w2 conversion folded into GEMM1 grid
constexpr int CVTY = 32;                 // 32 interleaved y-slices (x16 CTAs)
constexpr int CVT_THREADS = CVTY * 16 * NTH;         // 131072
constexpr long long W2_N8 = ((long long)kE * kD * kF) / 8;   // 8388608 uint4
}

// ---------------- scratch globals ----------------
__device__ int g_counts[kE];
__device__ int g_cursor[kE];
__device__ int g_rowtoken[TPAD];
__device__ int g_tile_expert[ROWT];
__device__ __half g_xperm[(size_t)TPAD * kD];     // permuted+padded fp16 tokens
__device__ __half g_w1h[(size_t)kE * kF * kD];
__device__ __half g_w2h[(size_t)kE * kD * kF];
__device__ __half g_h1h[(size_t)TPAD * kF];       // silu(x@w1^T) fp16

// ---------------- helpers ----------------
__device__ __forceinline__ uint32_t smem_u32(const void* p) {
    uint32_t a;
    asm("{ .reg .u64 t; cvta.to.shared.u64 t, %1; cvt.u32.u64 %0, t; }" : "=r"(a) : "l"(p));
    return a;
}
__device__ __forceinline__ void ldsm_x4(uint32_t* r, uint32_t addr) {
    asm volatile("ldmatrix.sync.aligned.m8n8.x4.shared.b16 {%0,%1,%2,%3}, [%4];"
                 : "=r"(r[0]), "=r"(r[1]), "=r"(r[2]), "=r"(r[3]) : "r"(addr));
}
__device__ __forceinline__ void mma_f16(float* c, const uint32_t* a, uint32_t b0, uint32_t b1) {
    asm volatile(
        "mma.sync.aligned.m16n8k16.row.col.f32.f16.f16.f32 "
        "{%0,%1,%2,%3}, {%4,%5,%6,%7}, {%8,%9}, {%0,%1,%2,%3};\n"
        : "+f"(c[0]), "+f"(c[1]), "+f"(c[2]), "+f"(c[3])
        : "r"(a[0]), "r"(a[1]), "r"(a[2]), "r"(a[3]), "r"(b0), "r"(b1));
}
__device__ __forceinline__ void cp_async16(uint32_t dst, const void* src) {
    asm volatile("cp.async.cg.shared.global [%0], [%1], 16;" :: "r"(dst), "l"(src));
}
__device__ __forceinline__ void cvt8(const float4* __restrict__ s, uint4* __restrict__ d) {
    float4 a = s[0], b = s[1];
    __half2 h0 = __floats2half2_rn(a.x, a.y), h1 = __floats2half2_rn(a.z, a.w);
    __half2 h2 = __floats2half2_rn(b.x, b.y), h3 = __floats2half2_rn(b.z, b.w);
    uint4 o;
    o.x = *(uint32_t*)&h0; o.y = *(uint32_t*)&h1;
    o.z = *(uint32_t*)&h2; o.w = *(uint32_t*)&h3;
    *d = o;
}

// ---------------- w1 convert (+ zero routing counters) ----------------
__global__ void k_cvt_w1(const float4* __restrict__ src, uint4* __restrict__ dst, int n8) {
    int i = blockIdx.x * blockDim.x + threadIdx.x;
    if (i < kE) g_counts[i] = 0;
    if (i >= n8) return;
    cvt8(src + 2 * (size_t)i, dst + i);
}

// ---------------- routing ----------------
__global__ void k_route(const float* __restrict__ logits) {
    int t = blockIdx.x * blockDim.x + threadIdx.x;
    if (t >= kT) return;
    const float* l = logits + (size_t)t * kE;
    int best = 0; float bv = l[0];
#pragma unroll
    for (int e = 1; e < kE; e++) { float v = l[e]; if (v > bv) { bv = v; best = e; } }
    atomicAdd(&g_counts[best], 1);
    ((int*)g_xperm)[t] = best;     // temp storage, overwritten by k_permute later
}
__global__ void k_offsets() {        // single block, 256 threads
    if (threadIdx.x == 0) {
        int off = 0;
        for (int e = 0; e < kE; e++) {
            g_cursor[e] = off;
            int nt = (g_counts[e] + TMm - 1) / TMm;
            for (int i = 0; i < nt; i++) g_tile_expert[off / TMm + i] = e;
            off += nt * TMm;
        }
        for (int rt = off / TMm; rt < ROWT; rt++) g_tile_expert[rt] = -1;
    }
    for (int i = threadIdx.x; i < TPAD; i += blockDim.x) g_rowtoken[i] = -1;
}
__global__ void k_scatter() {
    int t = blockIdx.x * blockDim.x + threadIdx.x;
    if (t >= kT) return;
    int e = ((int*)g_xperm)[t];
    int pos = atomicAdd(&g_cursor[e], 1);
    g_rowtoken[pos] = t;
}
// gather + fp32->fp16 convert + zero-pad into [TPAD, kD]
__global__ void k_permute(const float4* __restrict__ hs) {
    int i = blockIdx.x * blockDim.x + threadIdx.x;   // one per 8 halves
    int row = i >> 8;                                // kD/8 = 256 groups/row
    int q = i & 255;
    if (row >= TPAD) return;
    int tok = g_rowtoken[row];
    uint4 o = make_uint4(0, 0, 0, 0);
    if (tok >= 0) {
        const float4* s = hs + (size_t)tok * (kD / 4) + 2 * q;
        float4 a = s[0], b = s[1];
        __half2 h0 = __floats2half2_rn(a.x, a.y), h1 = __floats2half2_rn(a.z, a.w);
        __half2 h2 = __floats2half2_rn(b.x, b.y), h3 = __floats2half2_rn(b.z, b.w);
        o.x = *(uint32_t*)&h0; o.y = *(uint32_t*)&h1;
        o.z = *(uint32_t*)&h2; o.w = *(uint32_t*)&h3;
    }
    ((uint4*)g_xperm)[(size_t)row * 256 + q] = o;
}

// ---------------- fp16 HMMA GEMM (ldmatrix + 4-stage cp.async, 1 sync/chunk) --
// CTA tile 128x256, 8 warps (2 M x 4 N), warp tile 64x64.
// FIRST:  h1[TPAD,kF] = silu(g_xperm @ w1[e]^T); w2 fp16 conversion CTAs folded in.
// !FIRST: out[tok,kD] = g_h1h @ w2[e]^T   (scatter; pad rows dropped)
template <bool FIRST>
__global__ __launch_bounds__(NTH, 1) void k_gemm(const float4* __restrict__ w2src,
                                                 float* __restrict__ out)
{
    constexpr int N = FIRST ? kF : kD;
    constexpr int K = FIRST ? kD : kF;
    constexpr int NC = K / BK;

    int rt;
    if (FIRST) {
        // interleaved role mapping: y == 2 (mod 3) for y<96 -> w2 cvt slice
        const int y = blockIdx.y;
        if (y < 3 * CVTY && (y % 3) == 2) {
            const int slice = y / 3;
            long long base = ((long long)(slice * 16 + blockIdx.x) * NTH + threadIdx.x);
            uint4* dst = (uint4*)g_w2h;
#pragma unroll 4
            for (long long i = base; i < W2_N8; i += CVT_THREADS)
                cvt8(w2src + 2 * (size_t)i, dst + i);
            return;
        }
        rt = (y < 3 * CVTY) ? (y - (y + 1) / 3) : (y - CVTY);
    } else {
        rt = blockIdx.y;
    }

    const int e = g_tile_expert[rt];
    if (e < 0) return;
    const int rowbase = rt * TMm;
    const int colbase = blockIdx.x * TN;

    extern __shared__ char smem[];
    const uint32_t sb = smem_u32(smem);
    const int tid = threadIdx.x;
    const int warp = tid >> 5, lane = tid & 31;
    const int wm = warp & 1, wn = warp >> 1;

    const __half* Abase = FIRST ? g_xperm : g_h1h;
    const __half* Wb = (FIRST ? g_w1h : g_w2h) + (size_t)e * ((size_t)N * K);

    // ---- cp.async mapping: q = 16B group along K, r = base row ----
    const int q = tid & 7, r = tid >> 3;                 // r: 0..31
    const __half* aptr = Abase + (size_t)(rowbase + r) * K + q * 8;
    const __half* bptr = Wb + (size_t)(colbase + r) * K + q * 8;
    const uint32_t dA = (uint32_t)(r * 128 + ((q ^ (r & 7)) << 4));  // p*32 preserves row&7

    auto prefetch = [&](int c) {
        const uint32_t base = sb + (uint32_t)((c & (ST - 1)) * STG);
        const __half* ap = aptr + c * BK;
#pragma unroll
        for (int p = 0; p < 4; p++)
            cp_async16(base + dA + (uint32_t)(p * 32 * 128), ap + (size_t)p * 32 * K);
        const __half* bp = bptr + c * BK;
#pragma unroll
        for (int p = 0; p < 8; p++)
            cp_async16(base + A_BYTES + dA + (uint32_t)(p * 32 * 128), bp + (size_t)p * 32 * K);
        asm volatile("cp.async.commit_group;" ::: "memory");
    };

    prefetch(0);
    prefetch(1);
    prefetch(2);

    // ---- ldmatrix lane geometry ----
    const int rowA = wm * 64 + (lane & 15);
    const int kgA = lane >> 4;
    const int rowB = wn * 64 + ((lane >> 4) << 3) + (lane & 7);
    const int kgB = (lane >> 3) & 1;

    float acc[4][8][4];
#pragma unroll
    for (int i = 0; i < 4; i++)
#pragma unroll
        for (int j = 0; j < 8; j++)
#pragma unroll
            for (int v = 0; v < 4; v++) acc[i][j][v] = 0.f;

    for (int c = 0; c < NC; c++) {
        asm volatile("cp.async.wait_group 2;" ::: "memory");
        __syncthreads();                       // single barrier per chunk
        if (c + 3 < NC) prefetch(c + 3);       // safe: writes stage (c+3)&3, readers of it passed this sync

        const uint32_t stA = sb + (uint32_t)((c & (ST - 1)) * STG);
        const uint32_t stB = stA + A_BYTES;
#pragma unroll
        for (int s = 0; s < 4; s++) {     // 4 k16-steps
            uint32_t a[4][4];
#pragma unroll
            for (int mi = 0; mi < 4; mi++) {
                const int rr = rowA + mi * 16;
                ldsm_x4(a[mi], stA + (uint32_t)(rr * 128 + (((2 * s + kgA) ^ (rr & 7)) << 4)));
            }
            uint32_t b[4][4];
#pragma unroll
            for (int nj2 = 0; nj2 < 4; nj2++) {
                const int rr = rowB + nj2 * 16;
                ldsm_x4(b[nj2], stB + (uint32_t)(rr * 128 + (((2 * s + kgB) ^ (rr & 7)) << 4)));
            }
#pragma unroll
            for (int mi = 0; mi < 4; mi++)
#pragma unroll
                for (int nj = 0; nj < 8; nj++)
                    mma_f16(acc[mi][nj], a[mi], b[nj >> 1][(nj & 1) * 2], b[nj >> 1][(nj & 1) * 2 + 1]);
        }
    }

    // ---- epilogue ----
    const int g = lane >> 2, tig = lane & 3;
#pragma unroll
    for (int mi = 0; mi < 4; mi++) {
#pragma unroll
        for (int rr = 0; rr < 2; rr++) {
            const int lrow = rowbase + wm * 64 + mi * 16 + g + rr * 8;
            if (FIRST) {
                __half* hp = g_h1h + (size_t)lrow * kF + colbase;
#pragma unroll
                for (int nj = 0; nj < 8; nj++) {
                    const int col = wn * 64 + nj * 8 + tig * 2;
                    float v0 = acc[mi][nj][rr * 2 + 0];
                    float v1 = acc[mi][nj][rr * 2 + 1];
                    v0 = v0 / (1.f + __expf(-v0));       // SiLU
                    v1 = v1 / (1.f + __expf(-v1));
                    __half2 h = __floats2half2_rn(v0, v1);
                    *(uint32_t*)(hp + col) = *(uint32_t*)&h;
                }
            } else {
                const int tok = g_rowtoken[lrow];
                if (tok >= 0) {
                    float* op = out + (size_t)tok * kD + colbase;
#pragma unroll
                    for (int nj = 0; nj < 8; nj++) {
                        const int col = wn * 64 + nj * 8 + tig * 2;
                        float2 st;
                        st.x = acc[mi][nj][rr * 2 + 0];
                        st.y = acc[mi][nj][rr * 2 + 1];
                        *(float2*)(op + col) = st;
                    }
                }
            }
        }
    }
}

// ---------------- entry ----------------
extern "C" void kernel_launch(void* const* d_in, const int* in_sizes, int n_in,
                              void* d_out, int out_size) {
    const float* hs     = (const float*)d_in[0];
    const float* logits = (const float*)d_in[1];
    const float* w1     = (const float*)d_in[2];
    const float* w2     = (const float*)d_in[3];
    float* out = (float*)d_out;

    cudaFuncSetAttribute(k_gemm<true>,  cudaFuncAttributeMaxDynamicSharedMemorySize, SMEM_BYTES);
    cudaFuncSetAttribute(k_gemm<false>, cudaFuncAttributeMaxDynamicSharedMemorySize, SMEM_BYTES);

    void* p_w1h;
    cudaGetSymbolAddress(&p_w1h, g_w1h);

    // launch #1: w1 fp32->fp16 (+ zero routing counters)
    {
        long long n8 = ((long long)kE * kF * kD) / 8;
        k_cvt_w1<<<(unsigned)((n8 + 255) / 256), 256>>>((const float4*)w1, (uint4*)p_w1h, (int)n8);
    }
    // launches #2-#5: routing + permuted fp16 activations
    k_route<<<kT / 256, 256>>>(logits);
    k_offsets<<<1, 256>>>();
    k_scatter<<<kT / 256, 256>>>();
    k_permute<<<TPAD, 256>>>((const float4*)hs);

    // launch #6 (ncu -s 5 -c 1 captures this): GEMM1 with w2-conversion CTAs folded in
    dim3 g1(kF / TN, ROWT + CVTY);
    k_gemm<true><<<g1, NTH, SMEM_BYTES>>>((const float4*)w2, nullptr);
    // launch #7: GEMM2
    dim3 g2(kD / TN, ROWT);
    k_gemm<false><<<g2, NTH, SMEM_BYTES>>>(nullptr, out);
}